// round 15
// baseline (speedup 1.0000x reference)
#include <cuda_runtime.h>
#include <cuda_fp16.h>
#include <mma.h>
#include <math.h>
#include <stdint.h>

using namespace nvcuda;

#define BS 2
#define SEQ 2048
#define DIM 768
#define NH 12
#define HD 64
#define WINDOW 64
#define ROPE_BASE 10000.0f

#define QT 64
#define KTW 192
#define LDQ 72
#define LDKV 72
#define LDS 200
#define LDP 200
#define LDO 72
#define ATTN_SMEM (QT*LDQ*2 + KTW*LDKV*2 + QT*LDS*4 + QT*LDP*2)

#define MROWS 4096
#define KDIM 768

// ---- GEMM tiling: CTA 128x128, 4 warps (2x2) of 64x64, BK=32 fp16, 3 stages
#define GBM 128
#define GBN 128
#define GBK 32
#define GSTG 3
#define LDT 40
#define TILE_HALFS (GBM * LDT)
#define STAGE_HALFS (2 * TILE_HALFS)
#define PIPE_SMEM (GSTG * STAGE_HALFS * 2)          // 61440
#define LDC 132                                      // staging stride (floats); 528B = 33*16
#define QKV_SMEM (GBM * LDC * 4)                     // 67584
#define NKT (KDIM / GBK)

#define MODE_QKV 0
#define MODE_OUT 1

// ---------------- scratch ----------------------------------------------------
__device__ __half g_q[BS * NH * SEQ * HD];
__device__ __half g_k[BS * NH * SEQ * HD];
__device__ __half g_v[BS * NH * SEQ * HD];
__device__ __half g_hs_h[MROWS * DIM];
__device__ __half g_w1t[3 * DIM * DIM];
__device__ __half g_wot[DIM * DIM];
__device__ __half g_att[MROWS * DIM];
__device__ float2 g_rope[SEQ * 32];                  // (cos, sin) per (s, freq)

// ---------------- cp.async helpers -----------------------------------------
__device__ __forceinline__ uint32_t smem_u32(const void* p) {
    uint32_t a;
    asm("{ .reg .u64 t; cvta.to.shared.u64 t, %1; cvt.u32.u64 %0, t; }" : "=r"(a) : "l"(p));
    return a;
}
__device__ __forceinline__ void cp_async16(uint32_t dst, const void* src) {
    asm volatile("cp.async.cg.shared.global [%0], [%1], 16;" :: "r"(dst), "l"(src));
}
#define CP_COMMIT() asm volatile("cp.async.commit_group;" ::: "memory")
#define CP_WAIT(n)  asm volatile("cp.async.wait_group %0;" :: "n"(n) : "memory")

// ---------------- RoPE table -------------------------------------------------
__global__ void rope_table()
{
    int idx = blockIdx.x * blockDim.x + threadIdx.x;
    if (idx >= SEQ * 32) return;
    int s = idx >> 5, fi = idx & 31;
    float inv_freq = expf(-(2.0f * (float)fi / (float)HD) * logf(ROPE_BASE));
    float angle = (float)s * inv_freq;
    g_rope[idx] = make_float2(cosf(angle), sinf(angle));
}

// ---------------- fp16 mma GEMM: C[M,N] = A[M,768] @ Bt[N,768]^T -------------
// 128 threads, 4 warps (2x2) of 64x64 — round-7 mainloop.
// MODE_QKV: fused RoPE epilogue (table-driven) -> fp16 q/k/v in [b,h,s,d].
// MODE_OUT: plain fp32 C output.
template <int MODE>
__global__ __launch_bounds__(128) void gemm_f16(
    const __half* __restrict__ A, const __half* __restrict__ Bt,
    float* __restrict__ C, int N,
    __half* __restrict__ qo, __half* __restrict__ ko, __half* __restrict__ vo)
{
    extern __shared__ __half sm[];
    const uint32_t sbase = smem_u32(sm);
    const int tid = threadIdx.x;
    const int warp = tid >> 5;
    const int wm = warp >> 1;
    const int wn = warp & 1;
    const long bm = (long)blockIdx.y * GBM;
    const long bn = (long)blockIdx.x * GBN;

    wmma::fragment<wmma::accumulator, 16, 16, 16, float> acc[4][4];
#pragma unroll
    for (int i = 0; i < 4; i++)
#pragma unroll
        for (int j = 0; j < 4; j++) wmma::fill_fragment(acc[i][j], 0.0f);

    auto load_stage = [&](int buf, int k0) {
        uint32_t stage_base = sbase + (uint32_t)(buf * STAGE_HALFS * 2);
#pragma unroll
        for (int it = 0; it < 8; it++) {
            int c = tid + it * 128;
            int mat = c >> 9;
            int row = (c >> 2) & 127;
            int ch  = c & 3;
            const __half* g = (mat ? (Bt + (bn + row) * KDIM) : (A + (bm + row) * KDIM))
                              + k0 + ch * 8;
            uint32_t dst = stage_base + (uint32_t)((mat * TILE_HALFS + row * LDT + ch * 8) * 2);
            cp_async16(dst, g);
        }
    };

    load_stage(0, 0);
    CP_COMMIT();
    load_stage(1, GBK);
    CP_COMMIT();

#pragma unroll 1
    for (int kt = 0; kt < NKT; kt++) {
        CP_WAIT(GSTG - 2);
        __syncthreads();

        int nxt = kt + GSTG - 1;
        if (nxt < NKT) load_stage(nxt % GSTG, nxt * GBK);
        CP_COMMIT();

        const __half* As = sm + (kt % GSTG) * STAGE_HALFS;
        const __half* Bs = As + TILE_HALFS;
#pragma unroll
        for (int kk = 0; kk < GBK; kk += 16) {
            wmma::fragment<wmma::matrix_a, 16, 16, 16, __half, wmma::row_major> af[4];
            wmma::fragment<wmma::matrix_b, 16, 16, 16, __half, wmma::col_major> bf[4];
#pragma unroll
            for (int i = 0; i < 4; i++)
                wmma::load_matrix_sync(af[i], As + (wm * 64 + i * 16) * LDT + kk, LDT);
#pragma unroll
            for (int j = 0; j < 4; j++)
                wmma::load_matrix_sync(bf[j], Bs + (wn * 64 + j * 16) * LDT + kk, LDT);
#pragma unroll
            for (int i = 0; i < 4; i++)
#pragma unroll
                for (int j = 0; j < 4; j++)
                    wmma::mma_sync(acc[i][j], af[i], bf[j], acc[i][j]);
        }
    }

    if (MODE == MODE_OUT) {
#pragma unroll
        for (int i = 0; i < 4; i++)
#pragma unroll
            for (int j = 0; j < 4; j++)
                wmma::store_matrix_sync(
                    C + (bm + wm * 64 + i * 16) * N + bn + wn * 64 + j * 16,
                    acc[i][j], N, wmma::mem_row_major);
        return;
    }

    // ---- MODE_QKV: stage accumulators, apply table-driven RoPE, emit fp16 ----
    CP_WAIT(0);
    __syncthreads();
    float* stg = (float*)sm;
#pragma unroll
    for (int i = 0; i < 4; i++)
#pragma unroll
        for (int j = 0; j < 4; j++)
            wmma::store_matrix_sync(stg + (wm * 64 + i * 16) * LDC + wn * 64 + j * 16,
                                    acc[i][j], LDC, wmma::mem_row_major);
    __syncthreads();

    {
        const int row = tid;                 // 0..127
        const long mrow = bm + row;
        const int s = (int)(mrow & (SEQ - 1));
        const int b = (int)(mrow >> 11);
        const float2* rope = g_rope + s * 32;

#pragma unroll
        for (int hh = 0; hh < 2; hh++) {
            const int hoff = hh * 64;
            const int coln = (int)bn + hoff;
            const int sel = coln / DIM;      // 0=q 1=k 2=v
            const int h = (coln % DIM) / HD;

            __half* dst = (sel == 0 ? qo : sel == 1 ? ko : vo)
                          + ((long)(b * NH + h) * SEQ + s) * HD;
            const float* src = stg + row * LDC + hoff;

            if (sel == 2) {
#pragma unroll
                for (int c = 0; c < 64; c += 2) {
                    __half2 hv = __floats2half2_rn(src[c], src[c + 1]);
                    *(__half2*)(dst + c) = hv;
                }
            } else {
#pragma unroll
                for (int fi = 0; fi < 32; fi += 2) {
                    float x1a = src[fi],      x1b = src[fi + 1];
                    float x2a = src[fi + 32], x2b = src[fi + 33];
                    float2 r0 = rope[fi];
                    float2 r1 = rope[fi + 1];
                    __half2 lo = __floats2half2_rn(x1a * r0.x - x2a * r0.y,
                                                   x1b * r1.x - x2b * r1.y);
                    __half2 hi = __floats2half2_rn(x2a * r0.x + x1a * r0.y,
                                                   x2b * r1.x + x1b * r1.y);
                    *(__half2*)(dst + fi) = lo;
                    *(__half2*)(dst + fi + 32) = hi;
                }
            }
        }
    }
}

// ---------------- fp32 -> fp16 conversion -----------------------------------
__global__ void to_half(const float4* __restrict__ src, uint2* __restrict__ dst, int n4)
{
    int i = blockIdx.x * blockDim.x + threadIdx.x;
    if (i >= n4) return;
    float4 x = src[i];
    __half2 a = __floats2half2_rn(x.x, x.y);
    __half2 b = __floats2half2_rn(x.z, x.w);
    dst[i] = make_uint2(*(uint32_t*)&a, *(uint32_t*)&b);
}

__global__ void transpose_half(const float* __restrict__ src, __half* __restrict__ dst,
                               int Kd, int Nd)
{
    __shared__ float t[32][33];
    int n0 = blockIdx.x * 32, k0 = blockIdx.y * 32;
    int tx = threadIdx.x, ty = threadIdx.y;
#pragma unroll
    for (int r = 0; r < 4; r++)
        t[ty + r * 8][tx] = src[(size_t)(k0 + ty + r * 8) * Nd + n0 + tx];
    __syncthreads();
#pragma unroll
    for (int r = 0; r < 4; r++)
        dst[(size_t)(n0 + ty + r * 8) * Kd + k0 + tx] = __float2half_rn(t[tx][ty + r * 8]);
}

// ---------------- sliding-window attention (fp16 WMMA, fp32 softmax) --------
__global__ __launch_bounds__(256) void attn_kernel(
    const __half* __restrict__ q, const __half* __restrict__ k,
    const __half* __restrict__ v, __half* __restrict__ o)
{
    extern __shared__ char smraw[];
    __half* Qs  = (__half*)smraw;
    __half* KVs = Qs + QT * LDQ;
    float*  Ss  = (float*)(KVs + KTW * LDKV);
    __half* Ps  = (__half*)(Ss + QT * LDS);

    const int qt = blockIdx.x;
    const int h  = blockIdx.y;
    const int b  = blockIdx.z;
    const int i0 = qt * QT;
    const int j0 = i0 - WINDOW;
    const int tid = threadIdx.x;
    const int warp = tid >> 5;
    const int lane = tid & 31;

    const __half* Qg = q + ((long)(b * NH + h) * SEQ) * HD;
    const __half* Kg = k + ((long)(b * NH + h) * SEQ) * HD;
    const __half* Vg = v + ((long)(b * NH + h) * SEQ) * HD;

    for (int f = tid; f < QT * 8; f += 256) {
        int row = f >> 3, c8 = f & 7;
        uint4 val = *(const uint4*)(Qg + (long)(i0 + row) * HD + c8 * 8);
        *(uint4*)(Qs + row * LDQ + c8 * 8) = val;
    }
    for (int f = tid; f < KTW * 8; f += 256) {
        int row = f >> 3, c8 = f & 7;
        int j = j0 + row;
        uint4 val = make_uint4(0u, 0u, 0u, 0u);
        if (j >= 0 && j < SEQ) val = *(const uint4*)(Kg + (long)j * HD + c8 * 8);
        *(uint4*)(KVs + row * LDKV + c8 * 8) = val;
    }
    __syncthreads();

    // ---- S = Q @ K^T ----
    {
        const int wr = (warp & 3) * 16;
        const int wc = (warp >> 2) * 96;
        wmma::fragment<wmma::matrix_a, 16, 16, 16, __half, wmma::row_major> af[4];
#pragma unroll
        for (int kk = 0; kk < 4; kk++)
            wmma::load_matrix_sync(af[kk], Qs + wr * LDQ + kk * 16, LDQ);
#pragma unroll
        for (int jt = 0; jt < 6; jt++) {
            wmma::fragment<wmma::accumulator, 16, 16, 16, float> acc;
            wmma::fill_fragment(acc, 0.0f);
#pragma unroll
            for (int kk = 0; kk < 4; kk++) {
                wmma::fragment<wmma::matrix_b, 16, 16, 16, __half, wmma::col_major> bf;
                wmma::load_matrix_sync(bf, KVs + (wc + jt * 16) * LDKV + kk * 16, LDKV);
                wmma::mma_sync(acc, af[kk], bf, acc);
            }
            wmma::store_matrix_sync(Ss + wr * LDS + wc + jt * 16, acc, LDS, wmma::mem_row_major);
        }
    }
    __syncthreads();

    // ---- load V window ----
    for (int f = tid; f < KTW * 8; f += 256) {
        int row = f >> 3, c8 = f & 7;
        int j = j0 + row;
        uint4 val = make_uint4(0u, 0u, 0u, 0u);
        if (j >= 0 && j < SEQ) val = *(const uint4*)(Vg + (long)j * HD + c8 * 8);
        *(uint4*)(KVs + row * LDKV + c8 * 8) = val;
    }

    // ---- softmax ----
    {
        const float scale = 0.125f;
#pragma unroll
        for (int rr = 0; rr < 8; rr++) {
            int r = warp * 8 + rr;
            float e[6];
            float m = -INFINITY;
#pragma unroll
            for (int t = 0; t < 6; t++) {
                int c = lane + 32 * t;
                int jg = j0 + c;
                bool valid = (c >= r) && (c <= r + 2 * WINDOW) && (jg >= 0) && (jg < SEQ);
                float s = valid ? Ss[r * LDS + c] * scale : -INFINITY;
                e[t] = s;
                m = fmaxf(m, s);
            }
#pragma unroll
            for (int off = 16; off > 0; off >>= 1)
                m = fmaxf(m, __shfl_xor_sync(0xffffffffu, m, off));
            float sum = 0.0f;
#pragma unroll
            for (int t = 0; t < 6; t++) {
                e[t] = __expf(e[t] - m);
                sum += e[t];
            }
#pragma unroll
            for (int off = 16; off > 0; off >>= 1)
                sum += __shfl_xor_sync(0xffffffffu, sum, off);
            float inv = 1.0f / sum;
#pragma unroll
            for (int t = 0; t < 6; t++)
                Ps[r * LDP + lane + 32 * t] = __float2half_rn(e[t] * inv);
        }
    }
    __syncthreads();

    // ---- O = P @ V ----
    {
        const int wr = (warp & 3) * 16;
        const int wc = (warp >> 2) * 32;
        wmma::fragment<wmma::accumulator, 16, 16, 16, float> acc[2];
        wmma::fill_fragment(acc[0], 0.0f);
        wmma::fill_fragment(acc[1], 0.0f);
#pragma unroll
        for (int kk = 0; kk < 12; kk++) {
            wmma::fragment<wmma::matrix_a, 16, 16, 16, __half, wmma::row_major> af;
            wmma::load_matrix_sync(af, Ps + wr * LDP + kk * 16, LDP);
#pragma unroll
            for (int t = 0; t < 2; t++) {
                wmma::fragment<wmma::matrix_b, 16, 16, 16, __half, wmma::row_major> bf;
                wmma::load_matrix_sync(bf, KVs + kk * 16 * LDKV + wc + t * 16, LDKV);
                wmma::mma_sync(acc[t], af, bf, acc[t]);
            }
        }
#pragma unroll
        for (int t = 0; t < 2; t++)
            wmma::store_matrix_sync(Ss + wr * LDO + wc + t * 16, acc[t], LDO, wmma::mem_row_major);
    }
    __syncthreads();

    for (int idx = tid; idx < QT * 16; idx += 256) {
        int row = idx >> 4;
        int c4  = (idx & 15) * 4;
        const float* src = Ss + row * LDO + c4;
        __half2 h01 = __floats2half2_rn(src[0], src[1]);
        __half2 h23 = __floats2half2_rn(src[2], src[3]);
        long orow = ((long)(b * SEQ + i0 + row)) * DIM + h * HD + c4;
        *(uint2*)(o + orow) = make_uint2(*(uint32_t*)&h01, *(uint32_t*)&h23);
    }
}

// ---------------------------------------------------------------------------
extern "C" void kernel_launch(void* const* d_in, const int* in_sizes, int n_in,
                              void* d_out, int out_size)
{
    const float* hs   = (const float*)d_in[0];
    const float* Wqkv = (const float*)d_in[1];
    const float* Wo   = (const float*)d_in[2];
    float* out = (float*)d_out;

    __half *q, *k, *v, *hs_h, *w1t, *wot, *att;
    cudaGetSymbolAddress((void**)&q,    g_q);
    cudaGetSymbolAddress((void**)&k,    g_k);
    cudaGetSymbolAddress((void**)&v,    g_v);
    cudaGetSymbolAddress((void**)&hs_h, g_hs_h);
    cudaGetSymbolAddress((void**)&w1t,  g_w1t);
    cudaGetSymbolAddress((void**)&wot,  g_wot);
    cudaGetSymbolAddress((void**)&att,  g_att);

    cudaFuncSetAttribute(gemm_f16<MODE_QKV>, cudaFuncAttributeMaxDynamicSharedMemorySize, QKV_SMEM);
    cudaFuncSetAttribute(gemm_f16<MODE_OUT>, cudaFuncAttributeMaxDynamicSharedMemorySize, PIPE_SMEM);
    cudaFuncSetAttribute(attn_kernel, cudaFuncAttributeMaxDynamicSharedMemorySize, ATTN_SMEM);

    // 0) rope table + convert inputs to fp16
    {
        rope_table<<<(SEQ * 32 + 255) / 256, 256>>>();
        int n4 = MROWS * DIM / 4;
        to_half<<<(n4 + 255) / 256, 256>>>((const float4*)hs, (uint2*)hs_h, n4);
        transpose_half<<<dim3(3 * DIM / 32, DIM / 32), dim3(32, 8)>>>(Wqkv, w1t, DIM, 3 * DIM);
        transpose_half<<<dim3(DIM / 32, DIM / 32), dim3(32, 8)>>>(Wo, wot, DIM, DIM);
    }

    // 1) QKV projection + fused RoPE -> fp16 q/k/v [b,h,s,d]
    gemm_f16<MODE_QKV><<<dim3(3 * DIM / GBN, MROWS / GBM), 128, QKV_SMEM>>>(
        hs_h, w1t, nullptr, 3 * DIM, q, k, v);

    // 2) sliding-window attention
    {
        dim3 grid(SEQ / QT, NH, BS);
        attn_kernel<<<grid, 256, ATTN_SMEM>>>(q, k, v, att);
    }

    // 3) output projection
    gemm_f16<MODE_OUT><<<dim3(DIM / GBN, MROWS / GBM), 128, PIPE_SMEM>>>(
        att, wot, out, DIM, nullptr, nullptr, nullptr);
}

// round 16
// speedup vs baseline: 1.2291x; 1.2291x over previous
#include <cuda_runtime.h>
#include <cuda_fp16.h>
#include <mma.h>
#include <math.h>
#include <stdint.h>

using namespace nvcuda;

#define BS 2
#define SEQ 2048
#define DIM 768
#define NH 12
#define HD 64
#define WINDOW 64
#define ROPE_BASE 10000.0f

#define QT 64
#define KTW 192
#define LDQ 72
#define LDKV 72
#define LDS 200          // S stride (floats)
#define LDP 200          // P stride (halfs), aliased into S block
#define LDO 72           // O staging stride (floats), disjoint slice of S block
// S block layout (bytes): [0, 25600) P (aliases S rows after sync) | [25600, 44032) O staging
// S itself occupies [0, 51200) during the S phase.
#define ATTN_SMEM (QT*LDQ*2 + KTW*LDKV*2 + QT*LDS*4)   // 9216 + 27648 + 51200 = 88064

#define MROWS 4096
#define KDIM 768

// ---- GEMM tiling: CTA 128x128, 4 warps (2x2) of 64x64, BK=32 fp16, 3 stages
#define GBM 128
#define GBN 128
#define GBK 32
#define GSTG 3
#define LDT 40
#define TILE_HALFS (GBM * LDT)
#define STAGE_HALFS (2 * TILE_HALFS)
#define GEMM_SMEM (GSTG * STAGE_HALFS * 2)   // 61440
#define NKT (KDIM / GBK)

// ---------------- scratch ----------------------------------------------------
__device__ float  g_qkv[MROWS * 3 * DIM];
__device__ __half g_q[BS * NH * SEQ * HD];
__device__ __half g_k[BS * NH * SEQ * HD];
__device__ __half g_v[BS * NH * SEQ * HD];
__device__ __half g_hs_h[MROWS * DIM];
__device__ __half g_w1t[3 * DIM * DIM];
__device__ __half g_wot[DIM * DIM];
__device__ __half g_att[MROWS * DIM];
__device__ float2 g_rope[SEQ * 32];          // (cos, sin) per (s, freq)

// ---------------- cp.async helpers -----------------------------------------
__device__ __forceinline__ uint32_t smem_u32(const void* p) {
    uint32_t a;
    asm("{ .reg .u64 t; cvta.to.shared.u64 t, %1; cvt.u32.u64 %0, t; }" : "=r"(a) : "l"(p));
    return a;
}
__device__ __forceinline__ void cp_async16(uint32_t dst, const void* src) {
    asm volatile("cp.async.cg.shared.global [%0], [%1], 16;" :: "r"(dst), "l"(src));
}
#define CP_COMMIT() asm volatile("cp.async.commit_group;" ::: "memory")
#define CP_WAIT(n)  asm volatile("cp.async.wait_group %0;" :: "n"(n) : "memory")

// ---------------- RoPE table -------------------------------------------------
__global__ void rope_table()
{
    int idx = blockIdx.x * blockDim.x + threadIdx.x;
    if (idx >= SEQ * 32) return;
    int s = idx >> 5, fi = idx & 31;
    float inv_freq = expf(-(2.0f * (float)fi / (float)HD) * logf(ROPE_BASE));
    float angle = (float)s * inv_freq;
    g_rope[idx] = make_float2(cosf(angle), sinf(angle));
}

// ---------------- fp16 mma GEMM: C[M,N] = A[M,768] @ Bt[N,768]^T -------------
// Round-7 exact mainloop: 128 threads, 4 warps (2x2) of 64x64. Plain fp32 out.
__global__ __launch_bounds__(128) void gemm_f16(
    const __half* __restrict__ A, const __half* __restrict__ Bt,
    float* __restrict__ C, int N)
{
    extern __shared__ __half sm[];
    const uint32_t sbase = smem_u32(sm);
    const int tid = threadIdx.x;
    const int warp = tid >> 5;
    const int wm = warp >> 1;
    const int wn = warp & 1;
    const long bm = (long)blockIdx.y * GBM;
    const long bn = (long)blockIdx.x * GBN;

    wmma::fragment<wmma::accumulator, 16, 16, 16, float> acc[4][4];
#pragma unroll
    for (int i = 0; i < 4; i++)
#pragma unroll
        for (int j = 0; j < 4; j++) wmma::fill_fragment(acc[i][j], 0.0f);

    auto load_stage = [&](int buf, int k0) {
        uint32_t stage_base = sbase + (uint32_t)(buf * STAGE_HALFS * 2);
#pragma unroll
        for (int it = 0; it < 8; it++) {
            int c = tid + it * 128;
            int mat = c >> 9;
            int row = (c >> 2) & 127;
            int ch  = c & 3;
            const __half* g = (mat ? (Bt + (bn + row) * KDIM) : (A + (bm + row) * KDIM))
                              + k0 + ch * 8;
            uint32_t dst = stage_base + (uint32_t)((mat * TILE_HALFS + row * LDT + ch * 8) * 2);
            cp_async16(dst, g);
        }
    };

    load_stage(0, 0);
    CP_COMMIT();
    load_stage(1, GBK);
    CP_COMMIT();

#pragma unroll 1
    for (int kt = 0; kt < NKT; kt++) {
        CP_WAIT(GSTG - 2);
        __syncthreads();

        int nxt = kt + GSTG - 1;
        if (nxt < NKT) load_stage(nxt % GSTG, nxt * GBK);
        CP_COMMIT();

        const __half* As = sm + (kt % GSTG) * STAGE_HALFS;
        const __half* Bs = As + TILE_HALFS;
#pragma unroll
        for (int kk = 0; kk < GBK; kk += 16) {
            wmma::fragment<wmma::matrix_a, 16, 16, 16, __half, wmma::row_major> af[4];
            wmma::fragment<wmma::matrix_b, 16, 16, 16, __half, wmma::col_major> bf[4];
#pragma unroll
            for (int i = 0; i < 4; i++)
                wmma::load_matrix_sync(af[i], As + (wm * 64 + i * 16) * LDT + kk, LDT);
#pragma unroll
            for (int j = 0; j < 4; j++)
                wmma::load_matrix_sync(bf[j], Bs + (wn * 64 + j * 16) * LDT + kk, LDT);
#pragma unroll
            for (int i = 0; i < 4; i++)
#pragma unroll
                for (int j = 0; j < 4; j++)
                    wmma::mma_sync(acc[i][j], af[i], bf[j], acc[i][j]);
        }
    }

#pragma unroll
    for (int i = 0; i < 4; i++)
#pragma unroll
        for (int j = 0; j < 4; j++)
            wmma::store_matrix_sync(
                C + (bm + wm * 64 + i * 16) * N + bn + wn * 64 + j * 16,
                acc[i][j], N, wmma::mem_row_major);
}

// ---------------- fp32 -> fp16 conversion -----------------------------------
__global__ void to_half(const float4* __restrict__ src, uint2* __restrict__ dst, int n4)
{
    int i = blockIdx.x * blockDim.x + threadIdx.x;
    if (i >= n4) return;
    float4 x = src[i];
    __half2 a = __floats2half2_rn(x.x, x.y);
    __half2 b = __floats2half2_rn(x.z, x.w);
    dst[i] = make_uint2(*(uint32_t*)&a, *(uint32_t*)&b);
}

__global__ void transpose_half(const float* __restrict__ src, __half* __restrict__ dst,
                               int Kd, int Nd)
{
    __shared__ float t[32][33];
    int n0 = blockIdx.x * 32, k0 = blockIdx.y * 32;
    int tx = threadIdx.x, ty = threadIdx.y;
#pragma unroll
    for (int r = 0; r < 4; r++)
        t[ty + r * 8][tx] = src[(size_t)(k0 + ty + r * 8) * Nd + n0 + tx];
    __syncthreads();
#pragma unroll
    for (int r = 0; r < 4; r++)
        dst[(size_t)(n0 + ty + r * 8) * Kd + k0 + tx] = __float2half_rn(t[tx][ty + r * 8]);
}

// ---------------- RoPE + split/transpose -> fp16 q/k/v (table-driven) -------
__global__ void rope_split(const float* __restrict__ qkv,
                           __half* __restrict__ q, __half* __restrict__ k,
                           __half* __restrict__ v)
{
    int idx = blockIdx.x * blockDim.x + threadIdx.x;
    const int total = BS * SEQ * NH * HD;
    if (idx >= total) return;
    int d = idx % HD;
    int h = (idx / HD) % NH;
    int s = (idx / (HD * NH)) % SEQ;
    int b = idx / (HD * NH * SEQ);

    const float* base = qkv + (((long)(b * SEQ + s) * 3) * NH + h) * HD;
    float qv = base[d];
    float kv = base[NH * HD + d];
    float vv = base[2 * NH * HD + d];

    float2 r = g_rope[s * 32 + (d & 31)];
    float c = r.x, sn = r.y;

    float qo, ko;
    if (d < 32) {
        qo = qv * c - base[d + 32] * sn;
        ko = kv * c - base[NH * HD + d + 32] * sn;
    } else {
        qo = qv * c + base[d - 32] * sn;
        ko = kv * c + base[NH * HD + d - 32] * sn;
    }
    long out = ((long)(b * NH + h) * SEQ + s) * HD + d;
    q[out] = __float2half_rn(qo);
    k[out] = __float2half_rn(ko);
    v[out] = __float2half_rn(vv);
}

// ---------------- sliding-window attention (fp16 WMMA, fp32 softmax) --------
// Smem: Qs | KVs | Sblock. Sblock holds S (fp32, LDS) during the S phase;
// after softmax values are register-held, P (half, LDP) is written aliased at
// Sblock[0, 25600) and O staging (fp32, LDO) at Sblock[25600, 44032).
__global__ __launch_bounds__(256) void attn_kernel(
    const __half* __restrict__ q, const __half* __restrict__ k,
    const __half* __restrict__ v, __half* __restrict__ o)
{
    extern __shared__ char smraw[];
    __half* Qs  = (__half*)smraw;
    __half* KVs = Qs + QT * LDQ;
    float*  Ss  = (float*)(KVs + KTW * LDKV);
    __half* Ps  = (__half*)Ss;                          // alias, written after sync
    float*  Os  = (float*)((char*)Ss + QT * LDP * 2);   // disjoint from P region

    const int qt = blockIdx.x;
    const int h  = blockIdx.y;
    const int b  = blockIdx.z;
    const int i0 = qt * QT;
    const int j0 = i0 - WINDOW;
    const int tid = threadIdx.x;
    const int warp = tid >> 5;
    const int lane = tid & 31;

    const __half* Qg = q + ((long)(b * NH + h) * SEQ) * HD;
    const __half* Kg = k + ((long)(b * NH + h) * SEQ) * HD;
    const __half* Vg = v + ((long)(b * NH + h) * SEQ) * HD;

    for (int f = tid; f < QT * 8; f += 256) {
        int row = f >> 3, c8 = f & 7;
        uint4 val = *(const uint4*)(Qg + (long)(i0 + row) * HD + c8 * 8);
        *(uint4*)(Qs + row * LDQ + c8 * 8) = val;
    }
    for (int f = tid; f < KTW * 8; f += 256) {
        int row = f >> 3, c8 = f & 7;
        int j = j0 + row;
        uint4 val = make_uint4(0u, 0u, 0u, 0u);
        if (j >= 0 && j < SEQ) val = *(const uint4*)(Kg + (long)j * HD + c8 * 8);
        *(uint4*)(KVs + row * LDKV + c8 * 8) = val;
    }
    __syncthreads();

    // ---- S = Q @ K^T ----
    {
        const int wr = (warp & 3) * 16;
        const int wc = (warp >> 2) * 96;
        wmma::fragment<wmma::matrix_a, 16, 16, 16, __half, wmma::row_major> af[4];
#pragma unroll
        for (int kk = 0; kk < 4; kk++)
            wmma::load_matrix_sync(af[kk], Qs + wr * LDQ + kk * 16, LDQ);
#pragma unroll
        for (int jt = 0; jt < 6; jt++) {
            wmma::fragment<wmma::accumulator, 16, 16, 16, float> acc;
            wmma::fill_fragment(acc, 0.0f);
#pragma unroll
            for (int kk = 0; kk < 4; kk++) {
                wmma::fragment<wmma::matrix_b, 16, 16, 16, __half, wmma::col_major> bf;
                wmma::load_matrix_sync(bf, KVs + (wc + jt * 16) * LDKV + kk * 16, LDKV);
                wmma::mma_sync(acc, af[kk], bf, acc);
            }
            wmma::store_matrix_sync(Ss + wr * LDS + wc + jt * 16, acc, LDS, wmma::mem_row_major);
        }
    }
    __syncthreads();

    // ---- load V window (overlaps softmax S-reads; disjoint memory) ----
    for (int f = tid; f < KTW * 8; f += 256) {
        int row = f >> 3, c8 = f & 7;
        int j = j0 + row;
        uint4 val = make_uint4(0u, 0u, 0u, 0u);
        if (j >= 0 && j < SEQ) val = *(const uint4*)(Vg + (long)j * HD + c8 * 8);
        *(uint4*)(KVs + row * LDKV + c8 * 8) = val;
    }

    // ---- softmax: hold all 8 rows x 6 values in registers ----
    float e[8][6];
    {
        const float scale = 0.125f;
#pragma unroll
        for (int rr = 0; rr < 8; rr++) {
            int r = warp * 8 + rr;
            float m = -INFINITY;
#pragma unroll
            for (int t = 0; t < 6; t++) {
                int c = lane + 32 * t;
                int jg = j0 + c;
                bool valid = (c >= r) && (c <= r + 2 * WINDOW) && (jg >= 0) && (jg < SEQ);
                float s = valid ? Ss[r * LDS + c] * scale : -INFINITY;
                e[rr][t] = s;
                m = fmaxf(m, s);
            }
#pragma unroll
            for (int off = 16; off > 0; off >>= 1)
                m = fmaxf(m, __shfl_xor_sync(0xffffffffu, m, off));
            float sum = 0.0f;
#pragma unroll
            for (int t = 0; t < 6; t++) {
                e[rr][t] = __expf(e[rr][t] - m);
                sum += e[rr][t];
            }
#pragma unroll
            for (int off = 16; off > 0; off >>= 1)
                sum += __shfl_xor_sync(0xffffffffu, sum, off);
            float inv = 1.0f / sum;
#pragma unroll
            for (int t = 0; t < 6; t++) e[rr][t] *= inv;
        }
    }
    __syncthreads();     // all S reads done; V load complete

    // ---- write P (half) aliased over former S region ----
#pragma unroll
    for (int rr = 0; rr < 8; rr++) {
        int r = warp * 8 + rr;
#pragma unroll
        for (int t = 0; t < 6; t++)
            Ps[r * LDP + lane + 32 * t] = __float2half_rn(e[rr][t]);
    }
    __syncthreads();

    // ---- O = P @ V ----
    {
        const int wr = (warp & 3) * 16;
        const int wc = (warp >> 2) * 32;
        wmma::fragment<wmma::accumulator, 16, 16, 16, float> acc[2];
        wmma::fill_fragment(acc[0], 0.0f);
        wmma::fill_fragment(acc[1], 0.0f);
#pragma unroll
        for (int kk = 0; kk < 12; kk++) {
            wmma::fragment<wmma::matrix_a, 16, 16, 16, __half, wmma::row_major> af;
            wmma::load_matrix_sync(af, Ps + wr * LDP + kk * 16, LDP);
#pragma unroll
            for (int t = 0; t < 2; t++) {
                wmma::fragment<wmma::matrix_b, 16, 16, 16, __half, wmma::row_major> bf;
                wmma::load_matrix_sync(bf, KVs + kk * 16 * LDKV + wc + t * 16, LDKV);
                wmma::mma_sync(acc[t], af, bf, acc[t]);
            }
        }
#pragma unroll
        for (int t = 0; t < 2; t++)
            wmma::store_matrix_sync(Os + wr * LDO + wc + t * 16, acc[t], LDO, wmma::mem_row_major);
    }
    __syncthreads();

    for (int idx = tid; idx < QT * 16; idx += 256) {
        int row = idx >> 4;
        int c4  = (idx & 15) * 4;
        const float* src = Os + row * LDO + c4;
        __half2 h01 = __floats2half2_rn(src[0], src[1]);
        __half2 h23 = __floats2half2_rn(src[2], src[3]);
        long orow = ((long)(b * SEQ + i0 + row)) * DIM + h * HD + c4;
        *(uint2*)(o + orow) = make_uint2(*(uint32_t*)&h01, *(uint32_t*)&h23);
    }
}

// ---------------------------------------------------------------------------
extern "C" void kernel_launch(void* const* d_in, const int* in_sizes, int n_in,
                              void* d_out, int out_size)
{
    const float* hs   = (const float*)d_in[0];
    const float* Wqkv = (const float*)d_in[1];
    const float* Wo   = (const float*)d_in[2];
    float* out = (float*)d_out;

    float* qkv;
    __half *q, *k, *v, *hs_h, *w1t, *wot, *att;
    cudaGetSymbolAddress((void**)&qkv,  g_qkv);
    cudaGetSymbolAddress((void**)&q,    g_q);
    cudaGetSymbolAddress((void**)&k,    g_k);
    cudaGetSymbolAddress((void**)&v,    g_v);
    cudaGetSymbolAddress((void**)&hs_h, g_hs_h);
    cudaGetSymbolAddress((void**)&w1t,  g_w1t);
    cudaGetSymbolAddress((void**)&wot,  g_wot);
    cudaGetSymbolAddress((void**)&att,  g_att);

    cudaFuncSetAttribute(gemm_f16, cudaFuncAttributeMaxDynamicSharedMemorySize, GEMM_SMEM);
    cudaFuncSetAttribute(attn_kernel, cudaFuncAttributeMaxDynamicSharedMemorySize, ATTN_SMEM);

    // 0) rope table + convert inputs to fp16
    {
        rope_table<<<(SEQ * 32 + 255) / 256, 256>>>();
        int n4 = MROWS * DIM / 4;
        to_half<<<(n4 + 255) / 256, 256>>>((const float4*)hs, (uint2*)hs_h, n4);
        transpose_half<<<dim3(3 * DIM / 32, DIM / 32), dim3(32, 8)>>>(Wqkv, w1t, DIM, 3 * DIM);
        transpose_half<<<dim3(DIM / 32, DIM / 32), dim3(32, 8)>>>(Wo, wot, DIM, DIM);
    }

    // 1) QKV projection (fp16 HMMA, fp32 acc) -> fp32 qkv
    gemm_f16<<<dim3(3 * DIM / GBN, MROWS / GBM), 128, GEMM_SMEM>>>(hs_h, w1t, qkv, 3 * DIM);

    // 2) RoPE + split -> fp16 q/k/v (table-driven)
    {
        int total = BS * SEQ * NH * HD;
        rope_split<<<(total + 255) / 256, 256>>>(qkv, q, k, v);
    }

    // 3) sliding-window attention (2 CTAs/SM)
    {
        dim3 grid(SEQ / QT, NH, BS);
        attn_kernel<<<grid, 256, ATTN_SMEM>>>(q, k, v, att);
    }

    // 4) output projection
    gemm_f16<<<dim3(DIM / GBN, MROWS / GBM), 128, GEMM_SMEM>>>(att, wot, out, DIM);
}

// round 17
// speedup vs baseline: 1.2851x; 1.0455x over previous
#include <cuda_runtime.h>
#include <cuda_fp16.h>
#include <mma.h>
#include <math.h>
#include <stdint.h>

using namespace nvcuda;

#define BS 2
#define SEQ 2048
#define DIM 768
#define NH 12
#define HD 64
#define WINDOW 64
#define ROPE_BASE 10000.0f

#define QT 64
#define KTW 192
#define LDQ 72
#define LDKV 72
#define LDS 200          // S stride (floats)
#define LDP 200          // P stride (halfs), aliased into S block
#define LDO 72           // O staging stride (floats), disjoint slice of S block
#define ATTN_SMEM (QT*LDQ*2 + KTW*LDKV*2 + QT*LDS*4)   // 88064

#define MROWS 4096
#define KDIM 768

// ---- GEMM tiling: CTA 128x128, 4 warps (2x2) of 64x64, BK=32 fp16, 4 stages
#define GBM 128
#define GBN 128
#define GBK 32
#define GSTG 4
#define LDT 40
#define TILE_HALFS (GBM * LDT)
#define STAGE_HALFS (2 * TILE_HALFS)
#define GEMM_SMEM (GSTG * STAGE_HALFS * 2)   // 81920
#define NKT (KDIM / GBK)

// ---------------- scratch ----------------------------------------------------
__device__ float  g_qkv[MROWS * 3 * DIM];
__device__ __half g_q[BS * NH * SEQ * HD];
__device__ __half g_k[BS * NH * SEQ * HD];
__device__ __half g_v[BS * NH * SEQ * HD];
__device__ __half g_hs_h[MROWS * DIM];
__device__ __half g_w1t[3 * DIM * DIM];
__device__ __half g_wot[DIM * DIM];
__device__ __half g_att[MROWS * DIM];
__device__ float2 g_rope[SEQ * 32];          // (cos, sin) per (s, freq)

// ---------------- cp.async helpers -----------------------------------------
__device__ __forceinline__ uint32_t smem_u32(const void* p) {
    uint32_t a;
    asm("{ .reg .u64 t; cvta.to.shared.u64 t, %1; cvt.u32.u64 %0, t; }" : "=r"(a) : "l"(p));
    return a;
}
__device__ __forceinline__ void cp_async16(uint32_t dst, const void* src) {
    asm volatile("cp.async.cg.shared.global [%0], [%1], 16;" :: "r"(dst), "l"(src));
}
#define CP_COMMIT() asm volatile("cp.async.commit_group;" ::: "memory")
#define CP_WAIT(n)  asm volatile("cp.async.wait_group %0;" :: "n"(n) : "memory")

// ---------------- RoPE table -------------------------------------------------
__global__ void rope_table()
{
    int idx = blockIdx.x * blockDim.x + threadIdx.x;
    if (idx >= SEQ * 32) return;
    int s = idx >> 5, fi = idx & 31;
    float inv_freq = expf(-(2.0f * (float)fi / (float)HD) * logf(ROPE_BASE));
    float angle = (float)s * inv_freq;
    g_rope[idx] = make_float2(cosf(angle), sinf(angle));
}

// ---------------- fp16 mma GEMM: C[M,N] = A[M,768] @ Bt[N,768]^T -------------
// Proven mainloop: 128 threads, 4 warps (2x2) of 64x64. Plain fp32 out.
__global__ __launch_bounds__(128) void gemm_f16(
    const __half* __restrict__ A, const __half* __restrict__ Bt,
    float* __restrict__ C, int N)
{
    extern __shared__ __half sm[];
    const uint32_t sbase = smem_u32(sm);
    const int tid = threadIdx.x;
    const int warp = tid >> 5;
    const int wm = warp >> 1;
    const int wn = warp & 1;
    const long bm = (long)blockIdx.y * GBM;
    const long bn = (long)blockIdx.x * GBN;

    wmma::fragment<wmma::accumulator, 16, 16, 16, float> acc[4][4];
#pragma unroll
    for (int i = 0; i < 4; i++)
#pragma unroll
        for (int j = 0; j < 4; j++) wmma::fill_fragment(acc[i][j], 0.0f);

    auto load_stage = [&](int buf, int k0) {
        uint32_t stage_base = sbase + (uint32_t)(buf * STAGE_HALFS * 2);
#pragma unroll
        for (int it = 0; it < 8; it++) {
            int c = tid + it * 128;
            int mat = c >> 9;
            int row = (c >> 2) & 127;
            int ch  = c & 3;
            const __half* g = (mat ? (Bt + (bn + row) * KDIM) : (A + (bm + row) * KDIM))
                              + k0 + ch * 8;
            uint32_t dst = stage_base + (uint32_t)((mat * TILE_HALFS + row * LDT + ch * 8) * 2);
            cp_async16(dst, g);
        }
    };

    load_stage(0, 0);
    CP_COMMIT();
    load_stage(1, GBK);
    CP_COMMIT();
    load_stage(2, 2 * GBK);
    CP_COMMIT();

#pragma unroll 1
    for (int kt = 0; kt < NKT; kt++) {
        CP_WAIT(GSTG - 2);
        __syncthreads();

        int nxt = kt + GSTG - 1;
        if (nxt < NKT) load_stage(nxt % GSTG, nxt * GBK);
        CP_COMMIT();

        const __half* As = sm + (kt % GSTG) * STAGE_HALFS;
        const __half* Bs = As + TILE_HALFS;
#pragma unroll
        for (int kk = 0; kk < GBK; kk += 16) {
            wmma::fragment<wmma::matrix_a, 16, 16, 16, __half, wmma::row_major> af[4];
            wmma::fragment<wmma::matrix_b, 16, 16, 16, __half, wmma::col_major> bf[4];
#pragma unroll
            for (int i = 0; i < 4; i++)
                wmma::load_matrix_sync(af[i], As + (wm * 64 + i * 16) * LDT + kk, LDT);
#pragma unroll
            for (int j = 0; j < 4; j++)
                wmma::load_matrix_sync(bf[j], Bs + (wn * 64 + j * 16) * LDT + kk, LDT);
#pragma unroll
            for (int i = 0; i < 4; i++)
#pragma unroll
                for (int j = 0; j < 4; j++)
                    wmma::mma_sync(acc[i][j], af[i], bf[j], acc[i][j]);
        }
    }

#pragma unroll
    for (int i = 0; i < 4; i++)
#pragma unroll
        for (int j = 0; j < 4; j++)
            wmma::store_matrix_sync(
                C + (bm + wm * 64 + i * 16) * N + bn + wn * 64 + j * 16,
                acc[i][j], N, wmma::mem_row_major);
}

// ---------------- fp32 -> fp16 conversion -----------------------------------
__global__ void to_half(const float4* __restrict__ src, uint2* __restrict__ dst, int n4)
{
    int i = blockIdx.x * blockDim.x + threadIdx.x;
    if (i >= n4) return;
    float4 x = src[i];
    __half2 a = __floats2half2_rn(x.x, x.y);
    __half2 b = __floats2half2_rn(x.z, x.w);
    dst[i] = make_uint2(*(uint32_t*)&a, *(uint32_t*)&b);
}

__global__ void transpose_half(const float* __restrict__ src, __half* __restrict__ dst,
                               int Kd, int Nd)
{
    __shared__ float t[32][33];
    int n0 = blockIdx.x * 32, k0 = blockIdx.y * 32;
    int tx = threadIdx.x, ty = threadIdx.y;
#pragma unroll
    for (int r = 0; r < 4; r++)
        t[ty + r * 8][tx] = src[(size_t)(k0 + ty + r * 8) * Nd + n0 + tx];
    __syncthreads();
#pragma unroll
    for (int r = 0; r < 4; r++)
        dst[(size_t)(n0 + ty + r * 8) * Kd + k0 + tx] = __float2half_rn(t[tx][ty + r * 8]);
}

// ---------------- RoPE + split/transpose -> fp16 q/k/v (vectorized) ---------
// Thread handles dims [d4, d4+4) and [d4+32, d4+36) for one (b,s,h):
// 8 float4 loads, 6 uint2 stores, all coalesced.
__global__ void rope_split(const float* __restrict__ qkv,
                           __half* __restrict__ q, __half* __restrict__ k,
                           __half* __restrict__ v)
{
    int idx = blockIdx.x * blockDim.x + threadIdx.x;
    const int total = BS * SEQ * NH * 8;
    if (idx >= total) return;
    int d4 = (idx & 7) * 4;                 // 0,4,...,28
    int h  = (idx >> 3) % NH;
    int s  = (idx >> 3) / NH % SEQ;
    int b  = idx / (8 * NH * SEQ);

    const float* base = qkv + (((long)(b * SEQ + s) * 3) * NH + h) * HD;
    float4 qA = *(const float4*)(base + d4);
    float4 qB = *(const float4*)(base + d4 + 32);
    float4 kA = *(const float4*)(base + NH * HD + d4);
    float4 kB = *(const float4*)(base + NH * HD + d4 + 32);
    float4 vA = *(const float4*)(base + 2 * NH * HD + d4);
    float4 vB = *(const float4*)(base + 2 * NH * HD + d4 + 32);

    const float4* rp = (const float4*)(g_rope + s * 32 + d4);
    float4 r01 = rp[0];
    float4 r23 = rp[1];
    float cs[4] = { r01.x, r01.z, r23.x, r23.z };
    float sn[4] = { r01.y, r01.w, r23.y, r23.w };

    float qa[4] = { qA.x, qA.y, qA.z, qA.w }, qb[4] = { qB.x, qB.y, qB.z, qB.w };
    float ka[4] = { kA.x, kA.y, kA.z, kA.w }, kb[4] = { kB.x, kB.y, kB.z, kB.w };

    float qlo[4], qhi[4], klo[4], khi[4];
#pragma unroll
    for (int i = 0; i < 4; i++) {
        qlo[i] = qa[i] * cs[i] - qb[i] * sn[i];
        qhi[i] = qb[i] * cs[i] + qa[i] * sn[i];
        klo[i] = ka[i] * cs[i] - kb[i] * sn[i];
        khi[i] = kb[i] * cs[i] + ka[i] * sn[i];
    }

    long out = ((long)(b * NH + h) * SEQ + s) * HD;
    auto pack4 = [](float a0, float a1, float a2, float a3) {
        __half2 p0 = __floats2half2_rn(a0, a1);
        __half2 p1 = __floats2half2_rn(a2, a3);
        return make_uint2(*(uint32_t*)&p0, *(uint32_t*)&p1);
    };
    *(uint2*)(q + out + d4)      = pack4(qlo[0], qlo[1], qlo[2], qlo[3]);
    *(uint2*)(q + out + d4 + 32) = pack4(qhi[0], qhi[1], qhi[2], qhi[3]);
    *(uint2*)(k + out + d4)      = pack4(klo[0], klo[1], klo[2], klo[3]);
    *(uint2*)(k + out + d4 + 32) = pack4(khi[0], khi[1], khi[2], khi[3]);
    *(uint2*)(v + out + d4)      = pack4(vA.x, vA.y, vA.z, vA.w);
    *(uint2*)(v + out + d4 + 32) = pack4(vB.x, vB.y, vB.z, vB.w);
}

// ---------------- sliding-window attention (fp16 WMMA, fp32 softmax) --------
__global__ __launch_bounds__(256) void attn_kernel(
    const __half* __restrict__ q, const __half* __restrict__ k,
    const __half* __restrict__ v, __half* __restrict__ o)
{
    extern __shared__ char smraw[];
    __half* Qs  = (__half*)smraw;
    __half* KVs = Qs + QT * LDQ;
    float*  Ss  = (float*)(KVs + KTW * LDKV);
    __half* Ps  = (__half*)Ss;                          // alias, written after sync
    float*  Os  = (float*)((char*)Ss + QT * LDP * 2);   // disjoint from P region

    const int qt = blockIdx.x;
    const int h  = blockIdx.y;
    const int b  = blockIdx.z;
    const int i0 = qt * QT;
    const int j0 = i0 - WINDOW;
    const int tid = threadIdx.x;
    const int warp = tid >> 5;
    const int lane = tid & 31;

    const __half* Qg = q + ((long)(b * NH + h) * SEQ) * HD;
    const __half* Kg = k + ((long)(b * NH + h) * SEQ) * HD;
    const __half* Vg = v + ((long)(b * NH + h) * SEQ) * HD;

    for (int f = tid; f < QT * 8; f += 256) {
        int row = f >> 3, c8 = f & 7;
        uint4 val = *(const uint4*)(Qg + (long)(i0 + row) * HD + c8 * 8);
        *(uint4*)(Qs + row * LDQ + c8 * 8) = val;
    }
    for (int f = tid; f < KTW * 8; f += 256) {
        int row = f >> 3, c8 = f & 7;
        int j = j0 + row;
        uint4 val = make_uint4(0u, 0u, 0u, 0u);
        if (j >= 0 && j < SEQ) val = *(const uint4*)(Kg + (long)j * HD + c8 * 8);
        *(uint4*)(KVs + row * LDKV + c8 * 8) = val;
    }
    __syncthreads();

    // ---- S = Q @ K^T ----
    {
        const int wr = (warp & 3) * 16;
        const int wc = (warp >> 2) * 96;
        wmma::fragment<wmma::matrix_a, 16, 16, 16, __half, wmma::row_major> af[4];
#pragma unroll
        for (int kk = 0; kk < 4; kk++)
            wmma::load_matrix_sync(af[kk], Qs + wr * LDQ + kk * 16, LDQ);
#pragma unroll
        for (int jt = 0; jt < 6; jt++) {
            wmma::fragment<wmma::accumulator, 16, 16, 16, float> acc;
            wmma::fill_fragment(acc, 0.0f);
#pragma unroll
            for (int kk = 0; kk < 4; kk++) {
                wmma::fragment<wmma::matrix_b, 16, 16, 16, __half, wmma::col_major> bf;
                wmma::load_matrix_sync(bf, KVs + (wc + jt * 16) * LDKV + kk * 16, LDKV);
                wmma::mma_sync(acc, af[kk], bf, acc);
            }
            wmma::store_matrix_sync(Ss + wr * LDS + wc + jt * 16, acc, LDS, wmma::mem_row_major);
        }
    }
    __syncthreads();

    // ---- load V window (overlaps softmax S-reads; disjoint memory) ----
    for (int f = tid; f < KTW * 8; f += 256) {
        int row = f >> 3, c8 = f & 7;
        int j = j0 + row;
        uint4 val = make_uint4(0u, 0u, 0u, 0u);
        if (j >= 0 && j < SEQ) val = *(const uint4*)(Vg + (long)j * HD + c8 * 8);
        *(uint4*)(KVs + row * LDKV + c8 * 8) = val;
    }

    // ---- softmax: hold all 8 rows x 6 values in registers ----
    float e[8][6];
    {
        const float scale = 0.125f;
#pragma unroll
        for (int rr = 0; rr < 8; rr++) {
            int r = warp * 8 + rr;
            float m = -INFINITY;
#pragma unroll
            for (int t = 0; t < 6; t++) {
                int c = lane + 32 * t;
                int jg = j0 + c;
                bool valid = (c >= r) && (c <= r + 2 * WINDOW) && (jg >= 0) && (jg < SEQ);
                float s = valid ? Ss[r * LDS + c] * scale : -INFINITY;
                e[rr][t] = s;
                m = fmaxf(m, s);
            }
#pragma unroll
            for (int off = 16; off > 0; off >>= 1)
                m = fmaxf(m, __shfl_xor_sync(0xffffffffu, m, off));
            float sum = 0.0f;
#pragma unroll
            for (int t = 0; t < 6; t++) {
                e[rr][t] = __expf(e[rr][t] - m);
                sum += e[rr][t];
            }
#pragma unroll
            for (int off = 16; off > 0; off >>= 1)
                sum += __shfl_xor_sync(0xffffffffu, sum, off);
            float inv = 1.0f / sum;
#pragma unroll
            for (int t = 0; t < 6; t++) e[rr][t] *= inv;
        }
    }
    __syncthreads();     // all S reads done; V load complete

    // ---- write P (half) aliased over former S region ----
#pragma unroll
    for (int rr = 0; rr < 8; rr++) {
        int r = warp * 8 + rr;
#pragma unroll
        for (int t = 0; t < 6; t++)
            Ps[r * LDP + lane + 32 * t] = __float2half_rn(e[rr][t]);
    }
    __syncthreads();

    // ---- O = P @ V ----
    {
        const int wr = (warp & 3) * 16;
        const int wc = (warp >> 2) * 32;
        wmma::fragment<wmma::accumulator, 16, 16, 16, float> acc[2];
        wmma::fill_fragment(acc[0], 0.0f);
        wmma::fill_fragment(acc[1], 0.0f);
#pragma unroll
        for (int kk = 0; kk < 12; kk++) {
            wmma::fragment<wmma::matrix_a, 16, 16, 16, __half, wmma::row_major> af;
            wmma::load_matrix_sync(af, Ps + wr * LDP + kk * 16, LDP);
#pragma unroll
            for (int t = 0; t < 2; t++) {
                wmma::fragment<wmma::matrix_b, 16, 16, 16, __half, wmma::row_major> bf;
                wmma::load_matrix_sync(bf, KVs + kk * 16 * LDKV + wc + t * 16, LDKV);
                wmma::mma_sync(acc[t], af, bf, acc[t]);
            }
        }
#pragma unroll
        for (int t = 0; t < 2; t++)
            wmma::store_matrix_sync(Os + wr * LDO + wc + t * 16, acc[t], LDO, wmma::mem_row_major);
    }
    __syncthreads();

    for (int idx = tid; idx < QT * 16; idx += 256) {
        int row = idx >> 4;
        int c4  = (idx & 15) * 4;
        const float* src = Os + row * LDO + c4;
        __half2 h01 = __floats2half2_rn(src[0], src[1]);
        __half2 h23 = __floats2half2_rn(src[2], src[3]);
        long orow = ((long)(b * SEQ + i0 + row)) * DIM + h * HD + c4;
        *(uint2*)(o + orow) = make_uint2(*(uint32_t*)&h01, *(uint32_t*)&h23);
    }
}

// ---------------------------------------------------------------------------
extern "C" void kernel_launch(void* const* d_in, const int* in_sizes, int n_in,
                              void* d_out, int out_size)
{
    const float* hs   = (const float*)d_in[0];
    const float* Wqkv = (const float*)d_in[1];
    const float* Wo   = (const float*)d_in[2];
    float* out = (float*)d_out;

    float* qkv;
    __half *q, *k, *v, *hs_h, *w1t, *wot, *att;
    cudaGetSymbolAddress((void**)&qkv,  g_qkv);
    cudaGetSymbolAddress((void**)&q,    g_q);
    cudaGetSymbolAddress((void**)&k,    g_k);
    cudaGetSymbolAddress((void**)&v,    g_v);
    cudaGetSymbolAddress((void**)&hs_h, g_hs_h);
    cudaGetSymbolAddress((void**)&w1t,  g_w1t);
    cudaGetSymbolAddress((void**)&wot,  g_wot);
    cudaGetSymbolAddress((void**)&att,  g_att);

    cudaFuncSetAttribute(gemm_f16, cudaFuncAttributeMaxDynamicSharedMemorySize, GEMM_SMEM);
    cudaFuncSetAttribute(attn_kernel, cudaFuncAttributeMaxDynamicSharedMemorySize, ATTN_SMEM);

    // 0) rope table + convert inputs to fp16
    {
        rope_table<<<(SEQ * 32 + 255) / 256, 256>>>();
        int n4 = MROWS * DIM / 4;
        to_half<<<(n4 + 255) / 256, 256>>>((const float4*)hs, (uint2*)hs_h, n4);
        transpose_half<<<dim3(3 * DIM / 32, DIM / 32), dim3(32, 8)>>>(Wqkv, w1t, DIM, 3 * DIM);
        transpose_half<<<dim3(DIM / 32, DIM / 32), dim3(32, 8)>>>(Wo, wot, DIM, DIM);
    }

    // 1) QKV projection (fp16 HMMA, fp32 acc) -> fp32 qkv
    gemm_f16<<<dim3(3 * DIM / GBN, MROWS / GBM), 128, GEMM_SMEM>>>(hs_h, w1t, qkv, 3 * DIM);

    // 2) RoPE + split -> fp16 q/k/v (vectorized, table-driven)
    {
        int total = BS * SEQ * NH * 8;
        rope_split<<<(total + 255) / 256, 256>>>(qkv, q, k, v);
    }

    // 3) sliding-window attention (2 CTAs/SM)
    {
        dim3 grid(SEQ / QT, NH, BS);
        attn_kernel<<<grid, 256, ATTN_SMEM>>>(q, k, v, att);
    }

    // 4) output projection
    gemm_f16<<<dim3(DIM / GBN, MROWS / GBM), 128, GEMM_SMEM>>>(att, wot, out, DIM);
}